// round 11
// baseline (speedup 1.0000x reference)
#include <cuda_runtime.h>
#include <cstdint>
#include <math.h>

#define NB 4
#define NN 512
#define NC 128
#define EB 130816      // edges per batch = 511*512/2
#define CPB 909        // CTAs per batch (ceil(130816/144))
#define EPC 144        // edges per CTA: 128 tensor + 16 FFMA

// logit scratch (4 MB). Diagonal entries never written; softmax masks them exactly.
__device__ float g_logits[NB * NN * NN];

__device__ __forceinline__ uint32_t f2tf32(float f) {
    uint32_t r;
    asm("cvt.rna.tf32.f32 %0, %1;" : "=r"(r) : "f"(f));
    return r;
}
__device__ __forceinline__ float lrelu(float v) { return v > 0.f ? v : 0.01f * v; }
__device__ __forceinline__ uint32_t smem_u32(const void* p) {
    uint32_t a;
    asm("{ .reg .u64 t; cvta.to.shared.u64 t, %1; cvt.u32.u64 %0, t; }" : "=r"(a) : "l"(p));
    return a;
}

// D(16x8,f32) += A(16x8,tf32,row) * B(8x8,tf32,col)
__device__ __forceinline__ void mma8(float* d, uint32_t a0, uint32_t a1, uint32_t a2, uint32_t a3,
                                     uint32_t b0, uint32_t b1) {
    asm volatile("mma.sync.aligned.m16n8k8.row.col.f32.tf32.tf32.f32 "
                 "{%0,%1,%2,%3},{%4,%5,%6,%7},{%8,%9},{%0,%1,%2,%3};"
                 : "+f"(d[0]), "+f"(d[1]), "+f"(d[2]), "+f"(d[3])
                 : "r"(a0), "r"(a1), "r"(a2), "r"(a3), "r"(b0), "r"(b1));
}

__device__ __forceinline__ int perm32(int kk) { return (kk & 3) * 8 + (kk >> 2); }

#define CP_ASYNC4(dst_u32, src_ptr) \
    asm volatile("cp.async.ca.shared.global [%0], [%1], 4;" :: "r"(dst_u32), "l"(src_ptr) : "memory")
#define CP_COMMIT() asm volatile("cp.async.commit_group;" ::: "memory")
#define CP_WAIT0()  asm volatile("cp.async.wait_group 0;" ::: "memory")

// flat triangular decode: edge e (0..EB-1) -> (I, J), J > I
__device__ __forceinline__ void edge_decode(int e, int& I, int& J) {
    int i = (int)((1023.0f - sqrtf(fmaxf(0.0f, 1046529.0f - 8.0f * (float)e))) * 0.5f);
    i = i < 0 ? 0 : (i > 510 ? 510 : i);
    while (i * (1023 - i) / 2 > e) --i;
    while ((i + 1) * (1022 - i) / 2 <= e) ++i;
    I = i;
    J = i + 1 + (e - i * (1023 - i) / 2);
}

// Stage one 32-k chunk of W[N][K] into BOTH layouts:
// tensor (n*36 + perm32(kk)) and FFMA k-major (kk*193 + n). One commit group.
template <int N, int K>
__device__ __forceinline__ void stage_both(const float* __restrict__ src,
                                           uint32_t dstT, uint32_t dstF, int tid) {
    constexpr int PW = N >> 4;
#pragma unroll
    for (int p = 0; p < PW; ++p) {
        int idx = tid + (p << 9);
        int n = idx >> 5, kk = idx & 31;
        const float* s = src + n * K + kk;
        CP_ASYNC4(dstT + (uint32_t)((n * 36 + perm32(kk)) * 4), s);
        CP_ASYNC4(dstF + (uint32_t)((kk * 193 + n) * 4), s);
    }
    CP_COMMIT();
}

// Hybrid layer: tensor tile (128 rows, in-place buf) + 16 warp-private exact-fp32
// edges in actF (k-major, stride 17), FFMA woven between MMA batches.
// On entry: chunk0 committed (not waited) into sWa/sWFa. On last chunk stages
// next layer's chunk0 (NCH even for all layers with a successor).
template <int N, int K, int SA, int SO, int NEXTN, int NEXTK>
__device__ void layer(uint32_t* __restrict__ buf, float* __restrict__ actF,
                      const float* __restrict__ Wg, const float* __restrict__ bias,
                      const float* __restrict__ nextWg,
                      const uint32_t* __restrict__ sWa, const uint32_t* __restrict__ sWb,
                      const float* __restrict__ sWFa, const float* __restrict__ sWFb,
                      uint32_t swa, uint32_t swb, uint32_t swfa, uint32_t swfb, int tid)
{
    constexpr int NT  = N / 32;
    constexpr int NCH = K / 32;

    const int wid = tid >> 5, lane = tid & 31;
    const int g = lane >> 2, t = lane & 3;
    const int mb  = (wid & 3) * 32;
    const int nwb = (wid >> 2) * (N / 4);

    CP_WAIT0();
    __syncthreads();

    float d[2][NT][4];
#pragma unroll
    for (int mt = 0; mt < 2; ++mt)
#pragma unroll
        for (int nt = 0; nt < NT; ++nt)
#pragma unroll
            for (int q = 0; q < 4; ++q) d[mt][nt][q] = 0.f;
    float facc[NT];
#pragma unroll
    for (int m = 0; m < NT; ++m) facc[m] = 0.f;

    for (int c = 0; c < NCH; ++c) {
        if (c + 1 < NCH)
            stage_both<N, K>(Wg + (c + 1) * 32,
                             ((c + 1) & 1) ? swb : swa, ((c + 1) & 1) ? swfb : swfa, tid);
        else if (NEXTN > 0)
            stage_both<NEXTN, NEXTK>(nextWg, swa, swfa, tid);

        const uint32_t* sWc = (c & 1) ? sWb : sWa;
        const float* sWFc   = (c & 1) ? sWFb : sWFa;
#pragma unroll
        for (int h = 0; h < 2; ++h) {
            uint32_t bf[NT][4];
#pragma unroll
            for (int nt = 0; nt < NT; ++nt) {
                int n = nwb + nt * 8 + g;
                *(uint4*)bf[nt] = *(const uint4*)(sWc + n * 36 + t * 8 + 4 * h);
            }
            uint32_t av[2][2][4];
#pragma unroll
            for (int mt = 0; mt < 2; ++mt) {
                int r0 = mb + mt * 16 + g;
                *(uint4*)av[mt][0] = *(const uint4*)(buf + r0 * SA + c * 32 + t * 8 + 4 * h);
                *(uint4*)av[mt][1] = *(const uint4*)(buf + (r0 + 8) * SA + c * 32 + t * 8 + 4 * h);
            }
#pragma unroll
            for (int ks = 0; ks < 2; ++ks) {
#pragma unroll
                for (int mt = 0; mt < 2; ++mt)
#pragma unroll
                    for (int nt = 0; nt < NT; ++nt)
                        mma8(d[mt][nt],
                             av[mt][0][2 * ks], av[mt][1][2 * ks],
                             av[mt][0][2 * ks + 1], av[mt][1][2 * ks + 1],
                             bf[nt][2 * ks], bf[nt][2 * ks + 1]);
                // FFMA weave: 8 k-steps of the warp-private edge (fills mma stall slots)
                {
                    const int s0 = (h * 2 + ks) * 8;
                    const float* aFb = actF + (c * 32 + s0) * 17 + wid;
                    const float* wrb = sWFc + s0 * 193 + lane;
#pragma unroll
                    for (int kk = 0; kk < 8; ++kk) {
                        float avf = aFb[kk * 17];
#pragma unroll
                        for (int m = 0; m < NT; ++m)
                            facc[m] = fmaf(avf, wrb[kk * 193 + 32 * m], facc[m]);
                    }
                }
            }
        }
        if (c + 1 < NCH) CP_WAIT0();
        __syncthreads();
    }

    // tensor epilogue: bias + lrelu + tf32, in place, permuted columns
#pragma unroll
    for (int mt = 0; mt < 2; ++mt) {
        int r0 = mb + mt * 16 + g;
#pragma unroll
        for (int nt = 0; nt < NT; ++nt) {
            int cb = nwb + nt * 8 + 2 * t;
            float bb0 = bias[cb], bb1 = bias[cb + 1];
            int w0 = (cb >> 5) * 32 + perm32(cb & 31);
            int w1 = ((cb + 1) >> 5) * 32 + perm32((cb + 1) & 31);
            buf[r0 * SO + w0]       = f2tf32(lrelu(d[mt][nt][0] + bb0));
            buf[r0 * SO + w1]       = f2tf32(lrelu(d[mt][nt][1] + bb1));
            buf[(r0 + 8) * SO + w0] = f2tf32(lrelu(d[mt][nt][2] + bb0));
            buf[(r0 + 8) * SO + w1] = f2tf32(lrelu(d[mt][nt][3] + bb1));
        }
    }
    // FFMA epilogue: exact fp32, warp-private column (no sync needed)
#pragma unroll
    for (int m = 0; m < NT; ++m) {
        int col = lane + 32 * m;
        actF[col * 17 + wid] = lrelu(facc[m] + bias[col]);
    }
}

extern __shared__ uint32_t dynsm[];

__global__ void __launch_bounds__(512, 1)
mlp_kernel(const float* __restrict__ x,
           const float* __restrict__ w1, const float* __restrict__ b1,
           const float* __restrict__ w2, const float* __restrict__ b2,
           const float* __restrict__ w3, const float* __restrict__ b3,
           const float* __restrict__ w4, const float* __restrict__ b4,
           const float* __restrict__ w5, const float* __restrict__ b5)
{
    __shared__ int sI[EPC], sJ[EPC];
    __shared__ float sBias[576];
    __shared__ float sW5[96];
    __shared__ float sB5;

    const int tid = threadIdx.x;
    const int wid = tid >> 5, lane = tid & 31;

    const int blk = blockIdx.x;
    const int b = blk / CPB;
    const int eb0 = (blk - b * CPB) * EPC;

    const float* xb = x + (size_t)b * NN * NC;

    uint32_t* buf  = dynsm;                       // 128*196 = 25088 w
    uint32_t* sWa  = buf + 25088;                 // 192*36 = 6912 w
    uint32_t* sWb  = sWa + 6912;
    float* sWFa    = (float*)(sWb + 6912);        // 32*193 = 6176 w
    float* sWFb    = sWFa + 6176;
    float* actF    = sWFb + 6176;                 // 192*17 = 3264 w
    const uint32_t swa  = smem_u32(sWa),  swb  = smem_u32(sWb);
    const uint32_t swfa = smem_u32(sWFa), swfb = smem_u32(sWFb);

    // per-CTA edge decode + constants
    if (tid < EPC) {
        int e = eb0 + tid;
        if (e < EB) { int I, J; edge_decode(e, I, J); sI[tid] = I; sJ[tid] = J; }
        else        { sI[tid] = 0; sJ[tid] = -1; }
    }
    if (tid < 192) { sBias[tid] = b1[tid]; sBias[192 + tid] = b2[tid]; }
    if (tid < 96)  { sBias[384 + tid] = b3[tid]; sBias[480 + tid] = b4[tid]; sW5[tid] = w5[tid]; }
    if (tid == 0)  sB5 = b5[0];

    // stage L1 chunk0 (both layouts) while doing the prologue
    stage_both<192, 128>(w1, swa, swfa, tid);
    __syncthreads();   // sI/sJ ready

    // tensor prologue: buf[r][k] = tf32(|x_I[k] - x_J[k]|), stride 132, permuted
    for (int idx = tid; idx < 128 * 32; idx += 512) {
        int r = idx >> 5, kq = idx & 31;
        int I = sI[r], J = sJ[r];
        if (J < 0) { I = 0; J = 0; }
        float4 xi4 = *(const float4*)(xb + (size_t)I * NC + 4 * kq);
        float4 xj4 = *(const float4*)(xb + (size_t)J * NC + 4 * kq);
        uint32_t* dst = buf + r * 132 + (kq >> 3) * 32 + (kq & 7);
        dst[0]  = f2tf32(fabsf(xi4.x - xj4.x));
        dst[8]  = f2tf32(fabsf(xi4.y - xj4.y));
        dst[16] = f2tf32(fabsf(xi4.z - xj4.z));
        dst[24] = f2tf32(fabsf(xi4.w - xj4.w));
    }
    // FFMA prologue: warp-private edge 128+wid, exact fp32, k-major stride 17
    {
        int I = sI[128 + wid], J = sJ[128 + wid];
        if (J < 0) { I = 0; J = 0; }
        const float* xI = xb + (size_t)I * NC;
        const float* xJ = xb + (size_t)J * NC;
#pragma unroll
        for (int m = 0; m < 4; ++m) {
            int kg = lane + 32 * m;
            actF[kg * 17 + wid] = fabsf(xI[kg] - xJ[kg]);
        }
    }
    // layer entry performs CP_WAIT0 + __syncthreads (orders prologue writes too)

    layer<192, 128, 132, 196, 192, 192>(buf, actF, w1, sBias + 0,   w2, sWa, sWb, sWFa, sWFb, swa, swb, swfa, swfb, tid);
    layer<192, 192, 196, 196,  96, 192>(buf, actF, w2, sBias + 192, w3, sWa, sWb, sWFa, sWFb, swa, swb, swfa, swfb, tid);
    layer< 96, 192, 196, 100,  96,  96>(buf, actF, w3, sBias + 384, w4, sWa, sWb, sWFa, sWFb, swa, swb, swfa, swfb, tid);
    layer< 96,  96, 100, 100,   0,   0>(buf, actF, w4, sBias + 480, (const float*)0, sWa, sWb, sWFa, sWFb, swa, swb, swfa, swfb, tid);
    __syncthreads();   // layer-4 epilogues visible

    // tensor L5: 96 -> 1; 4 threads per row, permuted reads
    {
        const int r = tid >> 2, q = tid & 3;
        const uint32_t* arow = buf + r * 100;
        float acc = 0.f;
#pragma unroll
        for (int k = 0; k < 24; ++k) {
            int col = q * 24 + k;
            int w = (col >> 5) * 32 + perm32(col & 31);
            acc = fmaf(__uint_as_float(arow[w]), sW5[col], acc);
        }
        acc += __shfl_xor_sync(0xffffffffu, acc, 1);
        acc += __shfl_xor_sync(0xffffffffu, acc, 2);
        if (q == 0 && sJ[r] >= 0) {
            float lg = acc + sB5;
            int I = sI[r], J = sJ[r];
            g_logits[((size_t)b * NN + I) * NN + J] = lg;
            g_logits[((size_t)b * NN + J) * NN + I] = lg;
        }
    }
    // FFMA L5: warp-private edge
    {
        float acc5 = 0.f;
#pragma unroll
        for (int m = 0; m < 3; ++m) {
            int col = lane + 32 * m;
            acc5 = fmaf(actF[col * 17 + wid], sW5[col], acc5);
        }
#pragma unroll
        for (int o = 16; o > 0; o >>= 1) acc5 += __shfl_xor_sync(0xffffffffu, acc5, o);
        int J = sJ[128 + wid];
        if (lane == 0 && J >= 0) {
            float lg = acc5 + sB5;
            int I = sI[128 + wid];
            g_logits[((size_t)b * NN + I) * NN + J] = lg;
            g_logits[((size_t)b * NN + J) * NN + I] = lg;
        }
    }
}

__global__ void __launch_bounds__(256)
softmax_kernel(float2* __restrict__ out)
{
    __shared__ float sred[8];
    __shared__ float sval;
    int row = blockIdx.x;
    int i   = row & (NN - 1);
    const float* L = g_logits + (size_t)row * NN;
    int tid  = threadIdx.x;
    int lane = tid & 31, warp = tid >> 5;

    // self-edge masked exactly (diagonal logits are never computed)
    float l0 = (tid == i)       ? -1e8f : L[tid];
    float l1 = (tid + 256 == i) ? -1e8f : L[tid + 256];

    float m = fmaxf(l0, l1);
#pragma unroll
    for (int o = 16; o > 0; o >>= 1) m = fmaxf(m, __shfl_xor_sync(0xffffffffu, m, o));
    if (lane == 0) sred[warp] = m;
    __syncthreads();
    if (tid == 0) {
        float v = sred[0];
        for (int w = 1; w < 8; ++w) v = fmaxf(v, sred[w]);
        sval = v;
    }
    __syncthreads();
    float M  = sval;
    float e0 = expf(l0 - M);
    float e1 = expf(l1 - M);
    float s  = e0 + e1;
#pragma unroll
    for (int o = 16; o > 0; o >>= 1) s += __shfl_xor_sync(0xffffffffu, s, o);
    __syncthreads();
    if (lane == 0) sred[warp] = s;
    __syncthreads();
    if (tid == 0) {
        float v = 0.f;
        for (int w = 0; w < 8; ++w) v += sred[w];
        sval = 1.0f / v;
    }
    __syncthreads();
    float inv = sval;

    float2* o2 = out + (size_t)row * NN;
    o2[tid]       = make_float2(tid == i ? 1.f : 0.f,       e0 * inv);
    o2[tid + 256] = make_float2(tid + 256 == i ? 1.f : 0.f, e1 * inv);
}

extern "C" void kernel_launch(void* const* d_in, const int* in_sizes, int n_in,
                              void* d_out, int out_size)
{
    const float* x  = (const float*)d_in[0];
    // d_in[1] = W_id (exact identity; regenerated analytically)
    const float* w1 = (const float*)d_in[2];
    const float* b1 = (const float*)d_in[3];
    const float* w2 = (const float*)d_in[4];
    const float* b2 = (const float*)d_in[5];
    const float* w3 = (const float*)d_in[6];
    const float* b3 = (const float*)d_in[7];
    const float* w4 = (const float*)d_in[8];
    const float* b4 = (const float*)d_in[9];
    const float* w5 = (const float*)d_in[10];
    const float* b5 = (const float*)d_in[11];
    float2* out = (float2*)d_out;

    // dyn smem: buf 25088 + sWa/b 13824 + sWFa/b 12352 + actF 3264 = 54528 w = 218,112 B
    size_t smem_bytes = 54528 * sizeof(uint32_t);
    cudaFuncSetAttribute(mlp_kernel, cudaFuncAttributeMaxDynamicSharedMemorySize,
                         (int)smem_bytes);

    mlp_kernel<<<NB * CPB, 512, smem_bytes>>>(
        x, w1, b1, w2, b2, w3, b3, w4, b4, w5, b5);
    softmax_kernel<<<NB * NN, 256>>>(out);
}

// round 12
// speedup vs baseline: 1.6810x; 1.6810x over previous
#include <cuda_runtime.h>
#include <cstdint>
#include <math.h>

#define NB 4
#define NN 512
#define NC 128
#define EB 130816      // edges per batch = 511*512/2
#define EPC 64         // edges per CTA
#define CPB 2044       // CTAs per batch = EB/EPC (exact)

// logit scratch (4 MB). Diagonal entries never written; softmax masks them exactly.
__device__ float g_logits[NB * NN * NN];

__device__ __forceinline__ uint32_t f2tf32(float f) {
    uint32_t r;
    asm("cvt.rna.tf32.f32 %0, %1;" : "=r"(r) : "f"(f));
    return r;
}
__device__ __forceinline__ float lrelu(float v) { return v > 0.f ? v : 0.01f * v; }
__device__ __forceinline__ uint32_t smem_u32(const void* p) {
    uint32_t a;
    asm("{ .reg .u64 t; cvta.to.shared.u64 t, %1; cvt.u32.u64 %0, t; }" : "=r"(a) : "l"(p));
    return a;
}

// D(16x8,f32) += A(16x8,tf32,row) * B(8x8,tf32,col)
__device__ __forceinline__ void mma8(float* d, uint32_t a0, uint32_t a1, uint32_t a2, uint32_t a3,
                                     uint32_t b0, uint32_t b1) {
    asm volatile("mma.sync.aligned.m16n8k8.row.col.f32.tf32.tf32.f32 "
                 "{%0,%1,%2,%3},{%4,%5,%6,%7},{%8,%9},{%0,%1,%2,%3};"
                 : "+f"(d[0]), "+f"(d[1]), "+f"(d[2]), "+f"(d[3])
                 : "r"(a0), "r"(a1), "r"(a2), "r"(a3), "r"(b0), "r"(b1));
}

__device__ __forceinline__ int perm32(int kk) { return (kk & 3) * 8 + (kk >> 2); }

#define CP_ASYNC4(dst_u32, src_ptr) \
    asm volatile("cp.async.ca.shared.global [%0], [%1], 4;" :: "r"(dst_u32), "l"(src_ptr) : "memory")
#define CP_COMMIT() asm volatile("cp.async.commit_group;" ::: "memory")
#define CP_WAIT0()  asm volatile("cp.async.wait_group 0;" ::: "memory")

// flat triangular decode: edge e (0..EB-1) -> (I, J), J > I
__device__ __forceinline__ void edge_decode(int e, int& I, int& J) {
    int i = (int)((1023.0f - sqrtf(fmaxf(0.0f, 1046529.0f - 8.0f * (float)e))) * 0.5f);
    i = i < 0 ? 0 : (i > 510 ? 510 : i);
    while (i * (1023 - i) / 2 > e) --i;
    while ((i + 1) * (1022 - i) / 2 <= e) ++i;
    I = i;
    J = i + 1 + (e - i * (1023 - i) / 2);
}

// Stage one 32-k chunk of W[N][K] (src = &W[0][k0], row stride K) into SMEM
// (stride 36 words, permuted) via cp.async. 256 threads.
__device__ __forceinline__ void stage_chunk32(const float* __restrict__ src, int N, int K,
                                              uint32_t dstb, int tid) {
    int PW = N >> 3;
    for (int p = 0; p < PW; ++p) {
        int idx = tid + (p << 8);
        int n = idx >> 5, kk = idx & 31;
        CP_ASYNC4(dstb + (uint32_t)((n * 36 + perm32(kk)) * 4), src + n * K + kk);
    }
    CP_COMMIT();
}

// One MLP layer on a 64-row tile, in-place on `buf` (tf32 words; strides SA->SO, permuted).
// On entry: chunk0 committed (NOT waited) into sWa. On last chunk stages NEXT layer's
// chunk0 into sWa (NCH even where a successor exists).
// 8 warps: warp_m = wid&1 (32 rows), warp_n = wid>>1 (N/4 cols).
template <int N, int K, int SA, int SO, int NEXTN, int NEXTK>
__device__ void layer(uint32_t* __restrict__ buf,
                      const float* __restrict__ Wg, const float* __restrict__ bias,
                      const float* __restrict__ nextWg,
                      uint32_t* __restrict__ sWa, uint32_t* __restrict__ sWb,
                      uint32_t swa_bytes, uint32_t swb_bytes, int tid)
{
    constexpr int NT  = N / 32;     // 8-wide n-tiles per warp
    constexpr int NCH = K / 32;     // 4, 6, 6, 3

    const int wid = tid >> 5, lane = tid & 31;
    const int g = lane >> 2, t = lane & 3;
    const int mb  = (wid & 1) * 32;
    const int nwb = (wid >> 1) * (N / 4);

    CP_WAIT0();
    __syncthreads();

    float d[2][NT][4];
#pragma unroll
    for (int mt = 0; mt < 2; ++mt)
#pragma unroll
        for (int nt = 0; nt < NT; ++nt)
#pragma unroll
            for (int q = 0; q < 4; ++q) d[mt][nt][q] = 0.f;

    for (int c = 0; c < NCH; ++c) {
        if (c + 1 < NCH) {
            stage_chunk32(Wg + (c + 1) * 32, N, K,
                          ((c + 1) & 1) ? swb_bytes : swa_bytes, tid);
        } else if (NEXTN > 0) {
            stage_chunk32(nextWg, NEXTN, NEXTK, swa_bytes, tid);
        }
        const uint32_t* sWc = (c & 1) ? sWb : sWa;
#pragma unroll
        for (int h = 0; h < 2; ++h) {
            uint32_t bf[NT][4];
#pragma unroll
            for (int nt = 0; nt < NT; ++nt) {
                int n = nwb + nt * 8 + g;
                *(uint4*)bf[nt] = *(const uint4*)(sWc + n * 36 + t * 8 + 4 * h);
            }
            uint32_t av[2][2][4];
#pragma unroll
            for (int mt = 0; mt < 2; ++mt) {
                int r0 = mb + mt * 16 + g;
                *(uint4*)av[mt][0] = *(const uint4*)(buf + r0 * SA + c * 32 + t * 8 + 4 * h);
                *(uint4*)av[mt][1] = *(const uint4*)(buf + (r0 + 8) * SA + c * 32 + t * 8 + 4 * h);
            }
#pragma unroll
            for (int ks = 0; ks < 2; ++ks)
#pragma unroll
                for (int mt = 0; mt < 2; ++mt)
#pragma unroll
                    for (int nt = 0; nt < NT; ++nt)
                        mma8(d[mt][nt],
                             av[mt][0][2 * ks], av[mt][1][2 * ks],
                             av[mt][0][2 * ks + 1], av[mt][1][2 * ks + 1],
                             bf[nt][2 * ks], bf[nt][2 * ks + 1]);
        }
        if (c + 1 < NCH) CP_WAIT0();
        __syncthreads();
    }

    // epilogue: bias + lrelu + tf32, in place (inputs dead after last sync), permuted
#pragma unroll
    for (int mt = 0; mt < 2; ++mt) {
        int r0 = mb + mt * 16 + g;
#pragma unroll
        for (int nt = 0; nt < NT; ++nt) {
            int cb = nwb + nt * 8 + 2 * t;
            float bb0 = bias[cb], bb1 = bias[cb + 1];
            int w0 = (cb >> 5) * 32 + perm32(cb & 31);
            int w1 = ((cb + 1) >> 5) * 32 + perm32((cb + 1) & 31);
            buf[r0 * SO + w0]       = f2tf32(lrelu(d[mt][nt][0] + bb0));
            buf[r0 * SO + w1]       = f2tf32(lrelu(d[mt][nt][1] + bb1));
            buf[(r0 + 8) * SO + w0] = f2tf32(lrelu(d[mt][nt][2] + bb0));
            buf[(r0 + 8) * SO + w1] = f2tf32(lrelu(d[mt][nt][3] + bb1));
        }
    }
    // next layer's entry wait+sync orders the epilogue writes
}

extern __shared__ uint32_t dynsm[];

__global__ void __launch_bounds__(256, 2)
mlp_kernel(const float* __restrict__ x,
           const float* __restrict__ w1, const float* __restrict__ b1,
           const float* __restrict__ w2, const float* __restrict__ b2,
           const float* __restrict__ w3, const float* __restrict__ b3,
           const float* __restrict__ w4, const float* __restrict__ b4,
           const float* __restrict__ w5, const float* __restrict__ b5)
{
    __shared__ int sI[EPC], sJ[EPC];
    __shared__ float sBias[576];
    __shared__ float sW5[96];
    __shared__ float sB5;

    const int tid = threadIdx.x;

    const int blk = blockIdx.x;
    const int b = blk / CPB;
    const int eb0 = (blk - b * CPB) * EPC;

    const float* xb = x + (size_t)b * NN * NC;

    uint32_t* buf = dynsm;                 // 64*196 = 12544 words, in-place across layers
    uint32_t* sWa = buf + 64 * 196;        // 192*36 = 6912 words
    uint32_t* sWb = sWa + 6912;
    const uint32_t swa_bytes = smem_u32(sWa);
    const uint32_t swb_bytes = smem_u32(sWb);

    // per-CTA edge decode + constants
    if (tid < EPC) {
        int e = eb0 + tid;
        int I, J;
        edge_decode(e, I, J);
        sI[tid] = I; sJ[tid] = J;
    }
    if (tid < 192) { sBias[tid] = b1[tid]; sBias[192 + tid] = b2[tid]; }
    if (tid < 96)  { sBias[384 + tid] = b3[tid]; sBias[480 + tid] = b4[tid]; sW5[tid] = w5[tid]; }
    if (tid == 0)  sB5 = b5[0];

    // stage w1 chunk0 immediately (overlaps decode + prologue)
    stage_chunk32(w1, 192, 128, swa_bytes, tid);
    __syncthreads();   // sI/sJ ready

    // prologue: buf[r][k] = tf32(|x_I[k] - x_J[k]|), stride 132, permuted; float4 loads
    for (int idx = tid; idx < 64 * 32; idx += 256) {
        int r = idx >> 5, kq = idx & 31;
        float4 xi4 = *(const float4*)(xb + (size_t)sI[r] * NC + 4 * kq);
        float4 xj4 = *(const float4*)(xb + (size_t)sJ[r] * NC + 4 * kq);
        uint32_t* dst = buf + r * 132 + (kq >> 3) * 32 + (kq & 7);
        dst[0]  = f2tf32(fabsf(xi4.x - xj4.x));
        dst[8]  = f2tf32(fabsf(xi4.y - xj4.y));
        dst[16] = f2tf32(fabsf(xi4.z - xj4.z));
        dst[24] = f2tf32(fabsf(xi4.w - xj4.w));
    }
    // layer entry performs CP_WAIT0 + __syncthreads (orders prologue writes too)

    layer<192, 128, 132, 196, 192, 192>(buf, w1, sBias + 0,   w2, sWa, sWb, swa_bytes, swb_bytes, tid);
    layer<192, 192, 196, 196,  96, 192>(buf, w2, sBias + 192, w3, sWa, sWb, swa_bytes, swb_bytes, tid);
    layer< 96, 192, 196, 100,  96,  96>(buf, w3, sBias + 384, w4, sWa, sWb, swa_bytes, swb_bytes, tid);
    layer< 96,  96, 100, 100,   0,   0>(buf, w4, sBias + 480, (const float*)0, sWa, sWb, swa_bytes, swb_bytes, tid);
    __syncthreads();   // layer-4 epilogue visible

    // layer 5: 96 -> 1 (no activation); 4 threads per row, permuted reads
    {
        const int r = tid >> 2, q = tid & 3;
        const uint32_t* arow = buf + r * 100;
        float acc = 0.f;
#pragma unroll
        for (int k = 0; k < 24; ++k) {
            int col = q * 24 + k;
            int w = (col >> 5) * 32 + perm32(col & 31);
            acc = fmaf(__uint_as_float(arow[w]), sW5[col], acc);
        }
        acc += __shfl_xor_sync(0xffffffffu, acc, 1);
        acc += __shfl_xor_sync(0xffffffffu, acc, 2);
        if (q == 0) {
            float lg = acc + sB5;
            int I = sI[r], J = sJ[r];
            g_logits[((size_t)b * NN + I) * NN + J] = lg;   // direct
            g_logits[((size_t)b * NN + J) * NN + I] = lg;   // mirror (d symmetric)
        }
    }
}

__global__ void __launch_bounds__(256)
softmax_kernel(float2* __restrict__ out)
{
    __shared__ float sred[8];
    __shared__ float sval;
    int row = blockIdx.x;
    int i   = row & (NN - 1);
    const float* L = g_logits + (size_t)row * NN;
    int tid  = threadIdx.x;
    int lane = tid & 31, warp = tid >> 5;

    // self-edge masked exactly (diagonal logits are never computed)
    float l0 = (tid == i)       ? -1e8f : L[tid];
    float l1 = (tid + 256 == i) ? -1e8f : L[tid + 256];

    float m = fmaxf(l0, l1);
#pragma unroll
    for (int o = 16; o > 0; o >>= 1) m = fmaxf(m, __shfl_xor_sync(0xffffffffu, m, o));
    if (lane == 0) sred[warp] = m;
    __syncthreads();
    if (tid == 0) {
        float v = sred[0];
        for (int w = 1; w < 8; ++w) v = fmaxf(v, sred[w]);
        sval = v;
    }
    __syncthreads();
    float M  = sval;
    float e0 = expf(l0 - M);
    float e1 = expf(l1 - M);
    float s  = e0 + e1;
#pragma unroll
    for (int o = 16; o > 0; o >>= 1) s += __shfl_xor_sync(0xffffffffu, s, o);
    __syncthreads();
    if (lane == 0) sred[warp] = s;
    __syncthreads();
    if (tid == 0) {
        float v = 0.f;
        for (int w = 0; w < 8; ++w) v += sred[w];
        sval = 1.0f / v;
    }
    __syncthreads();
    float inv = sval;

    float2* o2 = out + (size_t)row * NN;
    o2[tid]       = make_float2(tid == i ? 1.f : 0.f,       e0 * inv);
    o2[tid + 256] = make_float2(tid + 256 == i ? 1.f : 0.f, e1 * inv);
}

extern "C" void kernel_launch(void* const* d_in, const int* in_sizes, int n_in,
                              void* d_out, int out_size)
{
    const float* x  = (const float*)d_in[0];
    // d_in[1] = W_id (exact identity; regenerated analytically)
    const float* w1 = (const float*)d_in[2];
    const float* b1 = (const float*)d_in[3];
    const float* w2 = (const float*)d_in[4];
    const float* b2 = (const float*)d_in[5];
    const float* w3 = (const float*)d_in[6];
    const float* b3 = (const float*)d_in[7];
    const float* w4 = (const float*)d_in[8];
    const float* b4 = (const float*)d_in[9];
    const float* w5 = (const float*)d_in[10];
    const float* b5 = (const float*)d_in[11];
    float2* out = (float2*)d_out;

    // dyn smem per CTA: act buf 64x196 + 2 weight buffers 192x36 = 26368 w = 105,472 B
    // -> 2 CTAs/SM (210,944 B <= 228 KB)
    size_t smem_bytes = (64 * 196 + 2 * 192 * 36) * sizeof(uint32_t);
    cudaFuncSetAttribute(mlp_kernel, cudaFuncAttributeMaxDynamicSharedMemorySize,
                         (int)smem_bytes);

    mlp_kernel<<<NB * CPB, 256, smem_bytes>>>(
        x, w1, b1, w2, b2, w3, b3, w4, b4, w5, b5);
    softmax_kernel<<<NB * NN, 256>>>(out);
}

// round 13
// speedup vs baseline: 1.8391x; 1.0940x over previous
#include <cuda_runtime.h>
#include <cstdint>
#include <math.h>

#define NB 4
#define NN 512
#define NC 128

// logit scratch (4 MB). Diagonal entries never written; softmax masks them exactly.
__device__ float g_logits[NB * NN * NN];

__device__ __forceinline__ uint32_t f2tf32(float f) {
    uint32_t r;
    asm("cvt.rna.tf32.f32 %0, %1;" : "=r"(r) : "f"(f));
    return r;
}
__device__ __forceinline__ float lrelu(float v) { return v > 0.f ? v : 0.01f * v; }
__device__ __forceinline__ uint32_t smem_u32(const void* p) {
    uint32_t a;
    asm("{ .reg .u64 t; cvta.to.shared.u64 t, %1; cvt.u32.u64 %0, t; }" : "=r"(a) : "l"(p));
    return a;
}

// D(16x8,f32) += A(16x8,tf32,row) * B(8x8,tf32,col)
__device__ __forceinline__ void mma8(float* d, uint32_t a0, uint32_t a1, uint32_t a2, uint32_t a3,
                                     uint32_t b0, uint32_t b1) {
    asm volatile("mma.sync.aligned.m16n8k8.row.col.f32.tf32.tf32.f32 "
                 "{%0,%1,%2,%3},{%4,%5,%6,%7},{%8,%9},{%0,%1,%2,%3};"
                 : "+f"(d[0]), "+f"(d[1]), "+f"(d[2]), "+f"(d[3])
                 : "r"(a0), "r"(a1), "r"(a2), "r"(a3), "r"(b0), "r"(b1));
}

__device__ __forceinline__ int perm32(int kk) { return (kk & 3) * 8 + (kk >> 2); }

#define CP_ASYNC4(dst_u32, src_ptr) \
    asm volatile("cp.async.ca.shared.global [%0], [%1], 4;" :: "r"(dst_u32), "l"(src_ptr) : "memory")
#define CP_COMMIT() asm volatile("cp.async.commit_group;" ::: "memory")
#define CP_WAIT0()  asm volatile("cp.async.wait_group 0;" ::: "memory")

// Stage one 32-k chunk of W[N][K] (src = &W[0][k0], row stride K) into SMEM
// (stride 36 words, permuted) via cp.async. 512 threads.
__device__ __forceinline__ void stage_chunk32(const float* __restrict__ src, int N, int K,
                                              uint32_t dstb, int tid) {
    int PW = N >> 4;
    for (int p = 0; p < PW; ++p) {
        int idx = tid + (p << 9);
        int n = idx >> 5, kk = idx & 31;
        CP_ASYNC4(dstb + (uint32_t)((n * 36 + perm32(kk)) * 4), src + n * K + kk);
    }
    CP_COMMIT();
}

// One MLP layer, in-place on `buf` (tf32 words; strides SA->SO, permuted k layout).
// On entry: this layer's chunk0 already committed (NOT waited) into sWa.
// On last chunk: stages NEXT layer's chunk0 into sWa.
// LAST=true: fuse layer-5 (96->1) into the epilogue — per-warp w5 partial dots,
// shuffle-reduced and atomically accumulated into srow (no buf writes, no extra pass).
// 16 warps: warp_m = wid&3 (32 rows), warp_n = wid>>2 (N/4 cols).
template <int N, int K, int SA, int SO, int NEXTN, int NEXTK, bool LAST>
__device__ void layer(uint32_t* __restrict__ buf,
                      const float* __restrict__ Wg, const float* __restrict__ bias,
                      const float* __restrict__ nextWg,
                      uint32_t* __restrict__ sWa, uint32_t* __restrict__ sWb,
                      uint32_t swa_bytes, uint32_t swb_bytes,
                      const float* __restrict__ sW5, float* __restrict__ srow, int tid)
{
    constexpr int NT  = N / 32;     // 8-wide n-tiles per warp
    constexpr int NCH = K / 32;     // 4, 6, 6, 3

    const int wid = tid >> 5, lane = tid & 31;
    const int g = lane >> 2, t = lane & 3;
    const int mb  = (wid & 3) * 32;
    const int nwb = (wid >> 2) * (N / 4);

    // entry: wait for chunk0 (committed by prev layer / prologue) + order A writes
    CP_WAIT0();
    __syncthreads();

    float d[2][NT][4];
#pragma unroll
    for (int mt = 0; mt < 2; ++mt)
#pragma unroll
        for (int nt = 0; nt < NT; ++nt)
#pragma unroll
            for (int q = 0; q < 4; ++q) d[mt][nt][q] = 0.f;

    for (int c = 0; c < NCH; ++c) {
        if (c + 1 < NCH) {
            stage_chunk32(Wg + (c + 1) * 32, N, K,
                          ((c + 1) & 1) ? swb_bytes : swa_bytes, tid);
        } else if (NEXTN > 0) {
            stage_chunk32(nextWg, NEXTN, NEXTK, swa_bytes, tid);
        }
        const uint32_t* sWc = (c & 1) ? sWb : sWa;
#pragma unroll
        for (int h = 0; h < 2; ++h) {
            uint32_t bf[NT][4];
#pragma unroll
            for (int nt = 0; nt < NT; ++nt) {
                int n = nwb + nt * 8 + g;
                *(uint4*)bf[nt] = *(const uint4*)(sWc + n * 36 + t * 8 + 4 * h);
            }
            uint32_t av[2][2][4];
#pragma unroll
            for (int mt = 0; mt < 2; ++mt) {
                int r0 = mb + mt * 16 + g;
                *(uint4*)av[mt][0] = *(const uint4*)(buf + r0 * SA + c * 32 + t * 8 + 4 * h);
                *(uint4*)av[mt][1] = *(const uint4*)(buf + (r0 + 8) * SA + c * 32 + t * 8 + 4 * h);
            }
#pragma unroll
            for (int ks = 0; ks < 2; ++ks)
#pragma unroll
                for (int mt = 0; mt < 2; ++mt)
#pragma unroll
                    for (int nt = 0; nt < NT; ++nt)
                        mma8(d[mt][nt],
                             av[mt][0][2 * ks], av[mt][1][2 * ks],
                             av[mt][0][2 * ks + 1], av[mt][1][2 * ks + 1],
                             bf[nt][2 * ks], bf[nt][2 * ks + 1]);
        }
        if (c + 1 < NCH) CP_WAIT0();
        __syncthreads();
    }

    if (!LAST) {
        // epilogue: bias + lrelu + tf32, in place (inputs dead after last sync), permuted
#pragma unroll
        for (int mt = 0; mt < 2; ++mt) {
            int r0 = mb + mt * 16 + g;
#pragma unroll
            for (int nt = 0; nt < NT; ++nt) {
                int cb = nwb + nt * 8 + 2 * t;
                float bb0 = bias[cb], bb1 = bias[cb + 1];
                int w0 = (cb >> 5) * 32 + perm32(cb & 31);
                int w1 = ((cb + 1) >> 5) * 32 + perm32((cb + 1) & 31);
                buf[r0 * SO + w0]       = f2tf32(lrelu(d[mt][nt][0] + bb0));
                buf[r0 * SO + w1]       = f2tf32(lrelu(d[mt][nt][1] + bb1));
                buf[(r0 + 8) * SO + w0] = f2tf32(lrelu(d[mt][nt][2] + bb0));
                buf[(r0 + 8) * SO + w1] = f2tf32(lrelu(d[mt][nt][3] + bb1));
            }
        }
    } else {
        // fused L4-epilogue + L5: v = lrelu(d+bias); partial dot with w5; reduce; atomicAdd
        float pr[2][2] = {{0.f, 0.f}, {0.f, 0.f}};   // [mt][row-half]
#pragma unroll
        for (int mt = 0; mt < 2; ++mt)
#pragma unroll
            for (int nt = 0; nt < NT; ++nt) {
                int cb = nwb + nt * 8 + 2 * t;
                float bb0 = bias[cb], bb1 = bias[cb + 1];
                float w50 = sW5[cb], w51 = sW5[cb + 1];
                pr[mt][0] = fmaf(lrelu(d[mt][nt][0] + bb0), w50, pr[mt][0]);
                pr[mt][0] = fmaf(lrelu(d[mt][nt][1] + bb1), w51, pr[mt][0]);
                pr[mt][1] = fmaf(lrelu(d[mt][nt][2] + bb0), w50, pr[mt][1]);
                pr[mt][1] = fmaf(lrelu(d[mt][nt][3] + bb1), w51, pr[mt][1]);
            }
        // reduce over the 4 col-pair threads (t = lane&3): xor 1, xor 2
#pragma unroll
        for (int mt = 0; mt < 2; ++mt)
#pragma unroll
            for (int hh = 0; hh < 2; ++hh) {
                pr[mt][hh] += __shfl_xor_sync(0xffffffffu, pr[mt][hh], 1);
                pr[mt][hh] += __shfl_xor_sync(0xffffffffu, pr[mt][hh], 2);
            }
        if (t == 0) {
#pragma unroll
            for (int mt = 0; mt < 2; ++mt) {
                atomicAdd(&srow[mb + mt * 16 + g],     pr[mt][0]);
                atomicAdd(&srow[mb + mt * 16 + 8 + g], pr[mt][1]);
            }
        }
    }
    // next layer's entry wait+sync orders the epilogue writes
}

extern __shared__ uint32_t dynsm[];

__global__ void __launch_bounds__(512, 1)
mlp_kernel(const float* __restrict__ x,
           const float* __restrict__ w1, const float* __restrict__ b1,
           const float* __restrict__ w2, const float* __restrict__ b2,
           const float* __restrict__ w3, const float* __restrict__ b3,
           const float* __restrict__ w4, const float* __restrict__ b4,
           const float* __restrict__ w5, const float* __restrict__ b5)
{
    __shared__ float sXi[256];     // [0:128) = x[I0], [128:256) = x[I1]
    __shared__ float sBias[576];
    __shared__ float sW5[96];
    __shared__ float sB5;
    __shared__ float srow[128];

    const int tid = threadIdx.x;

    // ---- exact-dedup tile decode: 1024 CTAs per batch (proven in R10) ----
    const int blk = blockIdx.x;
    const int b = blk >> 10;
    const int t = blk & 1023;
    int I0, I1, rsplit, jbase, pp = 0;
    bool isDiag = false;
    if (t < 384)      { I0 = t / 3;              jbase = 128 * (1 + t % 3); }
    else if (t < 640) { int l = t - 384; I0 = 128 + (l >> 1); jbase = 128 * (2 + (l & 1)); }
    else if (t < 768) { I0 = 256 + (t - 640);    jbase = 384; }
    else {
        isDiag = true;
        int dd = t - 768;
        int ibd = dd >> 6;
        pp = dd & 63;
        jbase = ibd * 128;
        I0 = jbase + pp;
        I1 = jbase + 127 - pp;
    }
    if (!isDiag) { I1 = I0; rsplit = 128; }
    else rsplit = 127 - pp;

    const float* xb = x + (size_t)b * NN * NC;

    uint32_t* buf = dynsm;                 // 128*196 words, in-place across layers
    uint32_t* sWa = buf + 128 * 196;       // 192*36 words
    uint32_t* sWb = sWa + 192 * 36;
    const uint32_t swa_bytes = smem_u32(sWa);
    const uint32_t swb_bytes = smem_u32(sWb);

    if (tid < 128)      { sXi[tid] = xb[(size_t)I0 * NC + tid]; srow[tid] = 0.f; }
    else if (tid < 256) sXi[tid] = xb[(size_t)I1 * NC + (tid - 128)];
    if (tid < 192) { sBias[tid] = b1[tid]; sBias[192 + tid] = b2[tid]; }
    if (tid < 96)  { sBias[384 + tid] = b3[tid]; sBias[480 + tid] = b4[tid]; sW5[tid] = w5[tid]; }
    if (tid == 0)  sB5 = b5[0];

    // stage w1 chunk0 immediately (overlaps xi staging + prologue)
    stage_chunk32(w1, 192, 128, swa_bytes, tid);
    __syncthreads();   // sXi ready

    // prologue: buf[r][k] = tf32(|x_I(r)[k] - x_J(r)[k]|), stride 132, permuted; float4 loads
    for (int idx = tid; idx < 128 * 32; idx += 512) {
        int r = idx >> 5, kq = idx & 31;
        int J;
        if (isDiag) J = (r == 127) ? jbase : (jbase + 1 + r + ((r < rsplit) ? pp : 0));
        else        J = jbase + r;
        const float* xi = sXi + ((r < rsplit) ? 0 : 128);
        float4 xj4 = *(const float4*)(xb + (size_t)J * NC + 4 * kq);
        float4 xi4 = *(const float4*)(xi + 4 * kq);
        uint32_t* dst = buf + r * 132 + (kq >> 3) * 32 + (kq & 7);
        dst[0]  = f2tf32(fabsf(xi4.x - xj4.x));
        dst[8]  = f2tf32(fabsf(xi4.y - xj4.y));
        dst[16] = f2tf32(fabsf(xi4.z - xj4.z));
        dst[24] = f2tf32(fabsf(xi4.w - xj4.w));
    }
    // layer entry performs CP_WAIT0 + __syncthreads (orders prologue writes too)

    layer<192, 128, 132, 196, 192, 192, false>(buf, w1, sBias + 0,   w2, sWa, sWb, swa_bytes, swb_bytes, sW5, srow, tid);
    layer<192, 192, 196, 196,  96, 192, false>(buf, w2, sBias + 192, w3, sWa, sWb, swa_bytes, swb_bytes, sW5, srow, tid);
    layer< 96, 192, 196, 100,  96,  96, false>(buf, w3, sBias + 384, w4, sWa, sWb, swa_bytes, swb_bytes, sW5, srow, tid);
    layer< 96,  96, 100, 100,   0,   0, true >(buf, w4, sBias + 480, (const float*)0, sWa, sWb, swa_bytes, swb_bytes, sW5, srow, tid);
    __syncthreads();   // srow atomics visible

    // write logits (fused L5 already accumulated in srow)
    if (tid < 128 && !(isDiag && tid == 127)) {
        float lg = srow[tid] + sB5;
        int I = (tid < rsplit) ? I0 : I1;
        int J;
        if (isDiag) J = jbase + 1 + tid + ((tid < rsplit) ? pp : 0);
        else        J = jbase + tid;
        g_logits[((size_t)b * NN + I) * NN + J] = lg;   // direct
        g_logits[((size_t)b * NN + J) * NN + I] = lg;   // mirror (d symmetric)
    }
}

__global__ void __launch_bounds__(256)
softmax_kernel(float2* __restrict__ out)
{
    __shared__ float sred[8];
    __shared__ float sval;
    int row = blockIdx.x;
    int i   = row & (NN - 1);
    const float* L = g_logits + (size_t)row * NN;
    int tid  = threadIdx.x;
    int lane = tid & 31, warp = tid >> 5;

    // self-edge masked exactly (diagonal logits are never computed)
    float l0 = (tid == i)       ? -1e8f : L[tid];
    float l1 = (tid + 256 == i) ? -1e8f : L[tid + 256];

    float m = fmaxf(l0, l1);
#pragma unroll
    for (int o = 16; o > 0; o >>= 1) m = fmaxf(m, __shfl_xor_sync(0xffffffffu, m, o));
    if (lane == 0) sred[warp] = m;
    __syncthreads();
    if (tid == 0) {
        float v = sred[0];
        for (int w = 1; w < 8; ++w) v = fmaxf(v, sred[w]);
        sval = v;
    }
    __syncthreads();
    float M  = sval;
    float e0 = expf(l0 - M);
    float e1 = expf(l1 - M);
    float s  = e0 + e1;
#pragma unroll
    for (int o = 16; o > 0; o >>= 1) s += __shfl_xor_sync(0xffffffffu, s, o);
    __syncthreads();
    if (lane == 0) sred[warp] = s;
    __syncthreads();
    if (tid == 0) {
        float v = 0.f;
        for (int w = 0; w < 8; ++w) v += sred[w];
        sval = 1.0f / v;
    }
    __syncthreads();
    float inv = sval;

    float2* o2 = out + (size_t)row * NN;
    o2[tid]       = make_float2(tid == i ? 1.f : 0.f,       e0 * inv);
    o2[tid + 256] = make_float2(tid + 256 == i ? 1.f : 0.f, e1 * inv);
}

extern "C" void kernel_launch(void* const* d_in, const int* in_sizes, int n_in,
                              void* d_out, int out_size)
{
    const float* x  = (const float*)d_in[0];
    // d_in[1] = W_id (exact identity; regenerated analytically)
    const float* w1 = (const float*)d_in[2];
    const float* b1 = (const float*)d_in[3];
    const float* w2 = (const float*)d_in[4];
    const float* b2 = (const float*)d_in[5];
    const float* w3 = (const float*)d_in[6];
    const float* b3 = (const float*)d_in[7];
    const float* w4 = (const float*)d_in[8];
    const float* b4 = (const float*)d_in[9];
    const float* w5 = (const float*)d_in[10];
    const float* b5 = (const float*)d_in[11];
    float2* out = (float2*)d_out;

    // dyn smem: act buf 128x196 + 2 weight chunk buffers 192x36 = 155,648 B
    size_t smem_bytes = (128 * 196 + 2 * 192 * 36) * sizeof(uint32_t);
    cudaFuncSetAttribute(mlp_kernel, cudaFuncAttributeMaxDynamicSharedMemorySize,
                         (int)smem_bytes);

    // exact-dedup tile set: 4 batches x 1024 CTAs
    mlp_kernel<<<NB * 1024, 512, smem_bytes>>>(
        x, w1, b1, w2, b2, w3, b3, w4, b4, w5, b5);
    softmax_kernel<<<NB * NN, 256>>>(out);
}

// round 14
// speedup vs baseline: 1.8595x; 1.0111x over previous
#include <cuda_runtime.h>
#include <cstdint>
#include <math.h>

#define NB 4
#define NN 512
#define NC 128

// logit scratch (4 MB). Diagonal entries never written; softmax masks them exactly.
__device__ float g_logits[NB * NN * NN];

#define WBUF_WORDS 6912        // 192*36 words per weight ring slot
#define WBUF_BYTES 27648

__device__ __forceinline__ uint32_t f2tf32(float f) {
    uint32_t r;
    asm("cvt.rna.tf32.f32 %0, %1;" : "=r"(r) : "f"(f));
    return r;
}
__device__ __forceinline__ float lrelu(float v) { return v > 0.f ? v : 0.01f * v; }
__device__ __forceinline__ uint32_t smem_u32(const void* p) {
    uint32_t a;
    asm("{ .reg .u64 t; cvta.to.shared.u64 t, %1; cvt.u32.u64 %0, t; }" : "=r"(a) : "l"(p));
    return a;
}

// D(16x8,f32) += A(16x8,tf32,row) * B(8x8,tf32,col)
__device__ __forceinline__ void mma8(float* d, uint32_t a0, uint32_t a1, uint32_t a2, uint32_t a3,
                                     uint32_t b0, uint32_t b1) {
    asm volatile("mma.sync.aligned.m16n8k8.row.col.f32.tf32.tf32.f32 "
                 "{%0,%1,%2,%3},{%4,%5,%6,%7},{%8,%9},{%0,%1,%2,%3};"
                 : "+f"(d[0]), "+f"(d[1]), "+f"(d[2]), "+f"(d[3])
                 : "r"(a0), "r"(a1), "r"(a2), "r"(a3), "r"(b0), "r"(b1));
}

__device__ __forceinline__ int perm32(int kk) { return (kk & 3) * 8 + (kk >> 2); }

#define CP_ASYNC4(dst_u32, src_ptr) \
    asm volatile("cp.async.ca.shared.global [%0], [%1], 4;" :: "r"(dst_u32), "l"(src_ptr) : "memory")
#define CP_COMMIT() asm volatile("cp.async.commit_group;" ::: "memory")
#define CP_WAIT0()  asm volatile("cp.async.wait_group 0;" ::: "memory")

// Stage one 32-k chunk of W[N][K] (src = &W[0][k0], row stride K) into SMEM
// (stride 36 words, permuted) via cp.async. 512 threads.
__device__ __forceinline__ void stage_chunk32(const float* __restrict__ src, int N, int K,
                                              uint32_t dstb, int tid) {
    int PW = N >> 4;
    for (int p = 0; p < PW; ++p) {
        int idx = tid + (p << 9);
        int n = idx >> 5, kk = idx & 31;
        CP_ASYNC4(dstb + (uint32_t)((n * 36 + perm32(kk)) * 4), src + n * K + kk);
    }
    CP_COMMIT();
}

// One MLP layer, in-place on `buf` (tf32 words; strides SA->SO, permuted k layout).
// 4-slot weight ring: chunk c lives in slot (BASE+c)&3. On entry: chunks 0,1 already
// committed (NOT waited). Stages two chunks ahead at even c (incl. next layer's 0,1
// during the last pair); ONE wait+barrier per chunk pair.
// LAST=true: fuse layer-5 (96->1) into the epilogue via srow atomics.
// 16 warps: warp_m = wid&3 (32 rows), warp_n = wid>>2 (N/4 cols).
template <int N, int K, int SA, int SO, int NEXTN, int NEXTK, int BASE, bool LAST>
__device__ void layer(uint32_t* __restrict__ buf,
                      const float* __restrict__ Wg, const float* __restrict__ bias,
                      const float* __restrict__ nextWg,
                      uint32_t* __restrict__ sW0, uint32_t sw0_bytes,
                      const float* __restrict__ sW5, float* __restrict__ srow, int tid)
{
    constexpr int NT  = N / 32;     // 8-wide n-tiles per warp
    constexpr int NCH = K / 32;     // 4, 6, 6, 3

    const int wid = tid >> 5, lane = tid & 31;
    const int g = lane >> 2, t = lane & 3;
    const int mb  = (wid & 3) * 32;
    const int nwb = (wid >> 2) * (N / 4);

    // entry: wait for chunks 0,1 (committed by prev layer / prologue) + order A writes
    CP_WAIT0();
    __syncthreads();

    float d[2][NT][4];
#pragma unroll
    for (int mt = 0; mt < 2; ++mt)
#pragma unroll
        for (int nt = 0; nt < NT; ++nt)
#pragma unroll
            for (int q = 0; q < 4; ++q) d[mt][nt][q] = 0.f;

    for (int c = 0; c < NCH; ++c) {
        if ((c & 1) == 0) {
            // stage two chunks ahead (slots free since the pair-(c/2-1) barrier)
            if (c + 2 < NCH)
                stage_chunk32(Wg + (c + 2) * 32, N, K,
                              sw0_bytes + (uint32_t)(((BASE + c + 2) & 3) * WBUF_BYTES), tid);
            else if (NEXTN > 0)
                stage_chunk32(nextWg, NEXTN, NEXTK,
                              sw0_bytes + (uint32_t)(((BASE + NCH) & 3) * WBUF_BYTES), tid);
            if (c + 3 < NCH)
                stage_chunk32(Wg + (c + 3) * 32, N, K,
                              sw0_bytes + (uint32_t)(((BASE + c + 3) & 3) * WBUF_BYTES), tid);
            else if (NEXTN > 0 && c + 2 >= NCH)
                stage_chunk32(nextWg + 32, NEXTN, NEXTK,
                              sw0_bytes + (uint32_t)(((BASE + NCH + 1) & 3) * WBUF_BYTES), tid);
        }
        const uint32_t* sWc = sW0 + ((BASE + c) & 3) * WBUF_WORDS;
#pragma unroll
        for (int h = 0; h < 2; ++h) {
            uint32_t bf[NT][4];
#pragma unroll
            for (int nt = 0; nt < NT; ++nt) {
                int n = nwb + nt * 8 + g;
                *(uint4*)bf[nt] = *(const uint4*)(sWc + n * 36 + t * 8 + 4 * h);
            }
            uint32_t av[2][2][4];
#pragma unroll
            for (int mt = 0; mt < 2; ++mt) {
                int r0 = mb + mt * 16 + g;
                *(uint4*)av[mt][0] = *(const uint4*)(buf + r0 * SA + c * 32 + t * 8 + 4 * h);
                *(uint4*)av[mt][1] = *(const uint4*)(buf + (r0 + 8) * SA + c * 32 + t * 8 + 4 * h);
            }
#pragma unroll
            for (int ks = 0; ks < 2; ++ks)
#pragma unroll
                for (int mt = 0; mt < 2; ++mt)
#pragma unroll
                    for (int nt = 0; nt < NT; ++nt)
                        mma8(d[mt][nt],
                             av[mt][0][2 * ks], av[mt][1][2 * ks],
                             av[mt][0][2 * ks + 1], av[mt][1][2 * ks + 1],
                             bf[nt][2 * ks], bf[nt][2 * ks + 1]);
        }
        if ((c & 1) == 1 || c == NCH - 1) { CP_WAIT0(); __syncthreads(); }
    }

    if (!LAST) {
        // epilogue: bias + lrelu + tf32, in place (inputs dead after final barrier), permuted
#pragma unroll
        for (int mt = 0; mt < 2; ++mt) {
            int r0 = mb + mt * 16 + g;
#pragma unroll
            for (int nt = 0; nt < NT; ++nt) {
                int cb = nwb + nt * 8 + 2 * t;
                float bb0 = bias[cb], bb1 = bias[cb + 1];
                int w0 = (cb >> 5) * 32 + perm32(cb & 31);
                int w1 = ((cb + 1) >> 5) * 32 + perm32((cb + 1) & 31);
                buf[r0 * SO + w0]       = f2tf32(lrelu(d[mt][nt][0] + bb0));
                buf[r0 * SO + w1]       = f2tf32(lrelu(d[mt][nt][1] + bb1));
                buf[(r0 + 8) * SO + w0] = f2tf32(lrelu(d[mt][nt][2] + bb0));
                buf[(r0 + 8) * SO + w1] = f2tf32(lrelu(d[mt][nt][3] + bb1));
            }
        }
    } else {
        // fused L4-epilogue + L5: v = lrelu(d+bias); partial dot with w5; reduce; atomicAdd
        float pr[2][2] = {{0.f, 0.f}, {0.f, 0.f}};   // [mt][row-half]
#pragma unroll
        for (int mt = 0; mt < 2; ++mt)
#pragma unroll
            for (int nt = 0; nt < NT; ++nt) {
                int cb = nwb + nt * 8 + 2 * t;
                float bb0 = bias[cb], bb1 = bias[cb + 1];
                float w50 = sW5[cb], w51 = sW5[cb + 1];
                pr[mt][0] = fmaf(lrelu(d[mt][nt][0] + bb0), w50, pr[mt][0]);
                pr[mt][0] = fmaf(lrelu(d[mt][nt][1] + bb1), w51, pr[mt][0]);
                pr[mt][1] = fmaf(lrelu(d[mt][nt][2] + bb0), w50, pr[mt][1]);
                pr[mt][1] = fmaf(lrelu(d[mt][nt][3] + bb1), w51, pr[mt][1]);
            }
#pragma unroll
        for (int mt = 0; mt < 2; ++mt)
#pragma unroll
            for (int hh = 0; hh < 2; ++hh) {
                pr[mt][hh] += __shfl_xor_sync(0xffffffffu, pr[mt][hh], 1);
                pr[mt][hh] += __shfl_xor_sync(0xffffffffu, pr[mt][hh], 2);
            }
        if (t == 0) {
#pragma unroll
            for (int mt = 0; mt < 2; ++mt) {
                atomicAdd(&srow[mb + mt * 16 + g],     pr[mt][0]);
                atomicAdd(&srow[mb + mt * 16 + 8 + g], pr[mt][1]);
            }
        }
    }
    // next layer's entry wait+sync orders the epilogue writes
}

extern __shared__ uint32_t dynsm[];

__global__ void __launch_bounds__(512, 1)
mlp_kernel(const float* __restrict__ x,
           const float* __restrict__ w1, const float* __restrict__ b1,
           const float* __restrict__ w2, const float* __restrict__ b2,
           const float* __restrict__ w3, const float* __restrict__ b3,
           const float* __restrict__ w4, const float* __restrict__ b4,
           const float* __restrict__ w5, const float* __restrict__ b5)
{
    __shared__ float sXi[256];     // [0:128) = x[I0], [128:256) = x[I1]
    __shared__ float sBias[576];
    __shared__ float sW5[96];
    __shared__ float sB5;
    __shared__ float srow[128];

    const int tid = threadIdx.x;

    // ---- exact-dedup tile decode: 1024 CTAs per batch (proven in R10/R13) ----
    const int blk = blockIdx.x;
    const int b = blk >> 10;
    const int t = blk & 1023;
    int I0, I1, rsplit, jbase, pp = 0;
    bool isDiag = false;
    if (t < 384)      { I0 = t / 3;              jbase = 128 * (1 + t % 3); }
    else if (t < 640) { int l = t - 384; I0 = 128 + (l >> 1); jbase = 128 * (2 + (l & 1)); }
    else if (t < 768) { I0 = 256 + (t - 640);    jbase = 384; }
    else {
        isDiag = true;
        int dd = t - 768;
        int ibd = dd >> 6;
        pp = dd & 63;
        jbase = ibd * 128;
        I0 = jbase + pp;
        I1 = jbase + 127 - pp;
    }
    if (!isDiag) { I1 = I0; rsplit = 128; }
    else rsplit = 127 - pp;

    const float* xb = x + (size_t)b * NN * NC;

    uint32_t* buf = dynsm;                 // 128*196 words, in-place across layers
    uint32_t* sW0 = buf + 128 * 196;       // 4-slot weight ring, 6912 words each
    const uint32_t sw0_bytes = smem_u32(sW0);

    if (tid < 128)      { sXi[tid] = xb[(size_t)I0 * NC + tid]; srow[tid] = 0.f; }
    else if (tid < 256) sXi[tid] = xb[(size_t)I1 * NC + (tid - 128)];
    if (tid < 192) { sBias[tid] = b1[tid]; sBias[192 + tid] = b2[tid]; }
    if (tid < 96)  { sBias[384 + tid] = b3[tid]; sBias[480 + tid] = b4[tid]; sW5[tid] = w5[tid]; }
    if (tid == 0)  sB5 = b5[0];

    // stage w1 chunks 0,1 immediately (slots 0,1; overlaps xi staging + prologue)
    stage_chunk32(w1,      192, 128, sw0_bytes,              tid);
    stage_chunk32(w1 + 32, 192, 128, sw0_bytes + WBUF_BYTES, tid);
    __syncthreads();   // sXi ready

    // prologue: buf[r][k] = tf32(|x_I(r)[k] - x_J(r)[k]|), stride 132, permuted; float4 loads
    for (int idx = tid; idx < 128 * 32; idx += 512) {
        int r = idx >> 5, kq = idx & 31;
        int J;
        if (isDiag) J = (r == 127) ? jbase : (jbase + 1 + r + ((r < rsplit) ? pp : 0));
        else        J = jbase + r;
        const float* xi = sXi + ((r < rsplit) ? 0 : 128);
        float4 xj4 = *(const float4*)(xb + (size_t)J * NC + 4 * kq);
        float4 xi4 = *(const float4*)(xi + 4 * kq);
        uint32_t* dst = buf + r * 132 + (kq >> 3) * 32 + (kq & 7);
        dst[0]  = f2tf32(fabsf(xi4.x - xj4.x));
        dst[8]  = f2tf32(fabsf(xi4.y - xj4.y));
        dst[16] = f2tf32(fabsf(xi4.z - xj4.z));
        dst[24] = f2tf32(fabsf(xi4.w - xj4.w));
    }
    // layer entry performs CP_WAIT0 + __syncthreads (orders prologue writes too)

    // ring BASE per layer: 0, (0+4)&3=0, (0+6)&3=2, (2+6)&3=0
    layer<192, 128, 132, 196, 192, 192, 0, false>(buf, w1, sBias + 0,   w2, sW0, sw0_bytes, sW5, srow, tid);
    layer<192, 192, 196, 196,  96, 192, 0, false>(buf, w2, sBias + 192, w3, sW0, sw0_bytes, sW5, srow, tid);
    layer< 96, 192, 196, 100,  96,  96, 2, false>(buf, w3, sBias + 384, w4, sW0, sw0_bytes, sW5, srow, tid);
    layer< 96,  96, 100, 100,   0,   0, 0, true >(buf, w4, sBias + 480, (const float*)0, sW0, sw0_bytes, sW5, srow, tid);
    __syncthreads();   // srow atomics visible

    // write logits (fused L5 already accumulated in srow)
    if (tid < 128 && !(isDiag && tid == 127)) {
        float lg = srow[tid] + sB5;
        int I = (tid < rsplit) ? I0 : I1;
        int J;
        if (isDiag) J = jbase + 1 + tid + ((tid < rsplit) ? pp : 0);
        else        J = jbase + tid;
        g_logits[((size_t)b * NN + I) * NN + J] = lg;   // direct
        g_logits[((size_t)b * NN + J) * NN + I] = lg;   // mirror (d symmetric)
    }
}

__global__ void __launch_bounds__(256)
softmax_kernel(float2* __restrict__ out)
{
    __shared__ float sred[8];
    __shared__ float sval;
    int row = blockIdx.x;
    int i   = row & (NN - 1);
    const float* L = g_logits + (size_t)row * NN;
    int tid  = threadIdx.x;
    int lane = tid & 31, warp = tid >> 5;

    // self-edge masked exactly (diagonal logits are never computed)
    float l0 = (tid == i)       ? -1e8f : L[tid];
    float l1 = (tid + 256 == i) ? -1e8f : L[tid + 256];

    float m = fmaxf(l0, l1);
#pragma unroll
    for (int o = 16; o > 0; o >>= 1) m = fmaxf(m, __shfl_xor_sync(0xffffffffu, m, o));
    if (lane == 0) sred[warp] = m;
    __syncthreads();
    if (tid == 0) {
        float v = sred[0];
        for (int w = 1; w < 8; ++w) v = fmaxf(v, sred[w]);
        sval = v;
    }
    __syncthreads();
    float M  = sval;
    float e0 = expf(l0 - M);
    float e1 = expf(l1 - M);
    float s  = e0 + e1;
#pragma unroll
    for (int o = 16; o > 0; o >>= 1) s += __shfl_xor_sync(0xffffffffu, s, o);
    __syncthreads();
    if (lane == 0) sred[warp] = s;
    __syncthreads();
    if (tid == 0) {
        float v = 0.f;
        for (int w = 0; w < 8; ++w) v += sred[w];
        sval = 1.0f / v;
    }
    __syncthreads();
    float inv = sval;

    float2* o2 = out + (size_t)row * NN;
    o2[tid]       = make_float2(tid == i ? 1.f : 0.f,       e0 * inv);
    o2[tid + 256] = make_float2(tid + 256 == i ? 1.f : 0.f, e1 * inv);
}

extern "C" void kernel_launch(void* const* d_in, const int* in_sizes, int n_in,
                              void* d_out, int out_size)
{
    const float* x  = (const float*)d_in[0];
    // d_in[1] = W_id (exact identity; regenerated analytically)
    const float* w1 = (const float*)d_in[2];
    const float* b1 = (const float*)d_in[3];
    const float* w2 = (const float*)d_in[4];
    const float* b2 = (const float*)d_in[5];
    const float* w3 = (const float*)d_in[6];
    const float* b3 = (const float*)d_in[7];
    const float* w4 = (const float*)d_in[8];
    const float* b4 = (const float*)d_in[9];
    const float* w5 = (const float*)d_in[10];
    const float* b5 = (const float*)d_in[11];
    float2* out = (float2*)d_out;

    // dyn smem: act buf 128x196 + 4-slot weight ring 4x6912 = 52736 words = 210,944 B
    size_t smem_bytes = (128 * 196 + 4 * WBUF_WORDS) * sizeof(uint32_t);
    cudaFuncSetAttribute(mlp_kernel, cudaFuncAttributeMaxDynamicSharedMemorySize,
                         (int)smem_bytes);

    // exact-dedup tile set: 4 batches x 1024 CTAs
    mlp_kernel<<<NB * 1024, 512, smem_bytes>>>(
        x, w1, b1, w2, b2, w3, b3, w4, b4, w5, b5);
    softmax_kernel<<<NB * NN, 256>>>(out);
}

// round 15
// speedup vs baseline: 1.8934x; 1.0182x over previous
#include <cuda_runtime.h>
#include <cstdint>
#include <math.h>

#define NB 4
#define NN 512
#define NC 128

// logit scratch (4 MB). Diagonal entries never written; softmax masks them exactly.
__device__ float g_logits[NB * NN * NN];

#define WBUF_WORDS 6912        // 192*36 words per weight ring slot
#define WBUF_BYTES 27648

__device__ __forceinline__ uint32_t f2tf32(float f) {
    uint32_t r;
    asm("cvt.rna.tf32.f32 %0, %1;" : "=r"(r) : "f"(f));
    return r;
}
__device__ __forceinline__ float lrelu(float v) { return v > 0.f ? v : 0.01f * v; }
__device__ __forceinline__ uint32_t smem_u32(const void* p) {
    uint32_t a;
    asm("{ .reg .u64 t; cvta.to.shared.u64 t, %1; cvt.u32.u64 %0, t; }" : "=r"(a) : "l"(p));
    return a;
}

// D(16x8,f32) += A(16x8,tf32,row) * B(8x8,tf32,col)
__device__ __forceinline__ void mma8(float* d, uint32_t a0, uint32_t a1, uint32_t a2, uint32_t a3,
                                     uint32_t b0, uint32_t b1) {
    asm volatile("mma.sync.aligned.m16n8k8.row.col.f32.tf32.tf32.f32 "
                 "{%0,%1,%2,%3},{%4,%5,%6,%7},{%8,%9},{%0,%1,%2,%3};"
                 : "+f"(d[0]), "+f"(d[1]), "+f"(d[2]), "+f"(d[3])
                 : "r"(a0), "r"(a1), "r"(a2), "r"(a3), "r"(b0), "r"(b1));
}

__device__ __forceinline__ int perm32(int kk) { return (kk & 3) * 8 + (kk >> 2); }

#define CP_ASYNC4(dst_u32, src_ptr) \
    asm volatile("cp.async.ca.shared.global [%0], [%1], 4;" :: "r"(dst_u32), "l"(src_ptr) : "memory")
#define CP_COMMIT() asm volatile("cp.async.commit_group;" ::: "memory")
#define CP_WAIT0()  asm volatile("cp.async.wait_group 0;" ::: "memory")

// Stage one 32-k chunk of W[N][K] (src = &W[0][k0], row stride K) into SMEM
// (stride 36 words, permuted) via cp.async. 512 threads.
__device__ __forceinline__ void stage_chunk32(const float* __restrict__ src, int N, int K,
                                              uint32_t dstb, int tid) {
    int PW = N >> 4;
    for (int p = 0; p < PW; ++p) {
        int idx = tid + (p << 9);
        int n = idx >> 5, kk = idx & 31;
        CP_ASYNC4(dstb + (uint32_t)((n * 36 + perm32(kk)) * 4), src + n * K + kk);
    }
    CP_COMMIT();
}

// Compute prologue chunk cc (cols 32cc..32cc+31) of A: buf[r][k]=tf32(|xi[k]-xj[k]|).
__device__ __forceinline__ void prologue_chunk(uint32_t* __restrict__ buf, int SA, int cc,
                                               const float* const* __restrict__ rowJ,
                                               const float* const* __restrict__ rowXi, int tid) {
    for (int idx = tid; idx < 128 * 8; idx += 512) {
        int r = idx >> 3, kq8 = idx & 7;
        int kq = cc * 8 + kq8;
        float4 xj4 = *(const float4*)(rowJ[r] + 4 * kq);
        float4 xi4 = *(const float4*)(rowXi[r] + 4 * kq);
        uint32_t* dst = buf + r * SA + cc * 32 + kq8;
        dst[0]  = f2tf32(fabsf(xi4.x - xj4.x));
        dst[8]  = f2tf32(fabsf(xi4.y - xj4.y));
        dst[16] = f2tf32(fabsf(xi4.z - xj4.z));
        dst[24] = f2tf32(fabsf(xi4.w - xj4.w));
    }
}

// One MLP layer, in-place on `buf` (tf32 words; strides SA->SO, permuted k layout).
// 4-slot weight ring: chunk c lives in slot (BASE+c)&3; one wait+barrier per chunk pair.
// PRO=true (layer 1): A chunks 2,3 are computed during MMA chunks 0,1 (pair barrier
// at c=1 orders the writes before their first read at c=2,3).
// LAST=true: fuse layer-5 (96->1) into the epilogue via srow atomics.
// 16 warps: warp_m = wid&3 (32 rows), warp_n = wid>>2 (N/4 cols).
template <int N, int K, int SA, int SO, int NEXTN, int NEXTK, int BASE, bool PRO, bool LAST>
__device__ void layer(uint32_t* __restrict__ buf,
                      const float* __restrict__ Wg, const float* __restrict__ bias,
                      const float* __restrict__ nextWg,
                      uint32_t* __restrict__ sW0, uint32_t sw0_bytes,
                      const float* __restrict__ sW5, float* __restrict__ srow,
                      const float* const* __restrict__ rowJ,
                      const float* const* __restrict__ rowXi, int tid)
{
    constexpr int NT  = N / 32;     // 8-wide n-tiles per warp
    constexpr int NCH = K / 32;     // 4, 6, 6, 3

    const int wid = tid >> 5, lane = tid & 31;
    const int g = lane >> 2, t = lane & 3;
    const int mb  = (wid & 3) * 32;
    const int nwb = (wid >> 2) * (N / 4);

    // entry: wait for chunks 0,1 (committed by prev layer / prologue) + order A writes
    CP_WAIT0();
    __syncthreads();

    float d[2][NT][4];
#pragma unroll
    for (int mt = 0; mt < 2; ++mt)
#pragma unroll
        for (int nt = 0; nt < NT; ++nt)
#pragma unroll
            for (int q = 0; q < 4; ++q) d[mt][nt][q] = 0.f;

    for (int c = 0; c < NCH; ++c) {
        if ((c & 1) == 0) {
            // stage two chunks ahead (slots free since the pair-(c/2-1) barrier)
            if (c + 2 < NCH)
                stage_chunk32(Wg + (c + 2) * 32, N, K,
                              sw0_bytes + (uint32_t)(((BASE + c + 2) & 3) * WBUF_BYTES), tid);
            else if (NEXTN > 0)
                stage_chunk32(nextWg, NEXTN, NEXTK,
                              sw0_bytes + (uint32_t)(((BASE + NCH) & 3) * WBUF_BYTES), tid);
            if (c + 3 < NCH)
                stage_chunk32(Wg + (c + 3) * 32, N, K,
                              sw0_bytes + (uint32_t)(((BASE + c + 3) & 3) * WBUF_BYTES), tid);
            else if (NEXTN > 0 && c + 2 >= NCH)
                stage_chunk32(nextWg + 32, NEXTN, NEXTK,
                              sw0_bytes + (uint32_t)(((BASE + NCH + 1) & 3) * WBUF_BYTES), tid);
        }
        // pipelined A prologue (layer 1 only): chunk c+2 during MMA chunk c (c=0,1)
        if (PRO && c < 2)
            prologue_chunk(buf, SA, c + 2, rowJ, rowXi, tid);

        const uint32_t* sWc = sW0 + ((BASE + c) & 3) * WBUF_WORDS;
#pragma unroll
        for (int h = 0; h < 2; ++h) {
            uint32_t bf[NT][4];
#pragma unroll
            for (int nt = 0; nt < NT; ++nt) {
                int n = nwb + nt * 8 + g;
                *(uint4*)bf[nt] = *(const uint4*)(sWc + n * 36 + t * 8 + 4 * h);
            }
            uint32_t av[2][2][4];
#pragma unroll
            for (int mt = 0; mt < 2; ++mt) {
                int r0 = mb + mt * 16 + g;
                *(uint4*)av[mt][0] = *(const uint4*)(buf + r0 * SA + c * 32 + t * 8 + 4 * h);
                *(uint4*)av[mt][1] = *(const uint4*)(buf + (r0 + 8) * SA + c * 32 + t * 8 + 4 * h);
            }
#pragma unroll
            for (int ks = 0; ks < 2; ++ks)
#pragma unroll
                for (int mt = 0; mt < 2; ++mt)
#pragma unroll
                    for (int nt = 0; nt < NT; ++nt)
                        mma8(d[mt][nt],
                             av[mt][0][2 * ks], av[mt][1][2 * ks],
                             av[mt][0][2 * ks + 1], av[mt][1][2 * ks + 1],
                             bf[nt][2 * ks], bf[nt][2 * ks + 1]);
        }
        if ((c & 1) == 1 || c == NCH - 1) { CP_WAIT0(); __syncthreads(); }
    }

    if (!LAST) {
        // epilogue: bias + lrelu + tf32, in place (inputs dead after final barrier), permuted
#pragma unroll
        for (int mt = 0; mt < 2; ++mt) {
            int r0 = mb + mt * 16 + g;
#pragma unroll
            for (int nt = 0; nt < NT; ++nt) {
                int cb = nwb + nt * 8 + 2 * t;
                float bb0 = bias[cb], bb1 = bias[cb + 1];
                int w0 = (cb >> 5) * 32 + perm32(cb & 31);
                int w1 = ((cb + 1) >> 5) * 32 + perm32((cb + 1) & 31);
                buf[r0 * SO + w0]       = f2tf32(lrelu(d[mt][nt][0] + bb0));
                buf[r0 * SO + w1]       = f2tf32(lrelu(d[mt][nt][1] + bb1));
                buf[(r0 + 8) * SO + w0] = f2tf32(lrelu(d[mt][nt][2] + bb0));
                buf[(r0 + 8) * SO + w1] = f2tf32(lrelu(d[mt][nt][3] + bb1));
            }
        }
    } else {
        // fused L4-epilogue + L5: v = lrelu(d+bias); partial dot with w5; reduce; atomicAdd
        float pr[2][2] = {{0.f, 0.f}, {0.f, 0.f}};   // [mt][row-half]
#pragma unroll
        for (int mt = 0; mt < 2; ++mt)
#pragma unroll
            for (int nt = 0; nt < NT; ++nt) {
                int cb = nwb + nt * 8 + 2 * t;
                float bb0 = bias[cb], bb1 = bias[cb + 1];
                float w50 = sW5[cb], w51 = sW5[cb + 1];
                pr[mt][0] = fmaf(lrelu(d[mt][nt][0] + bb0), w50, pr[mt][0]);
                pr[mt][0] = fmaf(lrelu(d[mt][nt][1] + bb1), w51, pr[mt][0]);
                pr[mt][1] = fmaf(lrelu(d[mt][nt][2] + bb0), w50, pr[mt][1]);
                pr[mt][1] = fmaf(lrelu(d[mt][nt][3] + bb1), w51, pr[mt][1]);
            }
#pragma unroll
        for (int mt = 0; mt < 2; ++mt)
#pragma unroll
            for (int hh = 0; hh < 2; ++hh) {
                pr[mt][hh] += __shfl_xor_sync(0xffffffffu, pr[mt][hh], 1);
                pr[mt][hh] += __shfl_xor_sync(0xffffffffu, pr[mt][hh], 2);
            }
        if (t == 0) {
#pragma unroll
            for (int mt = 0; mt < 2; ++mt) {
                atomicAdd(&srow[mb + mt * 16 + g],     pr[mt][0]);
                atomicAdd(&srow[mb + mt * 16 + 8 + g], pr[mt][1]);
            }
        }
    }
    // next layer's entry wait+sync orders the epilogue writes
}

extern __shared__ uint32_t dynsm[];

__global__ void __launch_bounds__(512, 1)
mlp_kernel(const float* __restrict__ x,
           const float* __restrict__ w1, const float* __restrict__ b1,
           const float* __restrict__ w2, const float* __restrict__ b2,
           const float* __restrict__ w3, const float* __restrict__ b3,
           const float* __restrict__ w4, const float* __restrict__ b4,
           const float* __restrict__ w5, const float* __restrict__ b5)
{
    __shared__ float sXi[256];     // [0:128) = x[I0], [128:256) = x[I1]
    __shared__ float sBias[576];
    __shared__ float sW5[96];
    __shared__ float sB5;
    __shared__ float srow[128];
    __shared__ const float* sRowJ[128];
    __shared__ const float* sRowXi[128];

    const int tid = threadIdx.x;

    // ---- exact-dedup tile decode: 1024 CTAs per batch (proven in R10/R13/R14) ----
    const int blk = blockIdx.x;
    const int b = blk >> 10;
    const int t = blk & 1023;
    int I0, I1, rsplit, jbase, pp = 0;
    bool isDiag = false;
    if (t < 384)      { I0 = t / 3;              jbase = 128 * (1 + t % 3); }
    else if (t < 640) { int l = t - 384; I0 = 128 + (l >> 1); jbase = 128 * (2 + (l & 1)); }
    else if (t < 768) { I0 = 256 + (t - 640);    jbase = 384; }
    else {
        isDiag = true;
        int dd = t - 768;
        int ibd = dd >> 6;
        pp = dd & 63;
        jbase = ibd * 128;
        I0 = jbase + pp;
        I1 = jbase + 127 - pp;
    }
    if (!isDiag) { I1 = I0; rsplit = 128; }
    else rsplit = 127 - pp;

    const float* xb = x + (size_t)b * NN * NC;

    uint32_t* buf = dynsm;                 // 128*196 words, in-place across layers
    uint32_t* sW0 = buf + 128 * 196;       // 4-slot weight ring, 6912 words each
    const uint32_t sw0_bytes = smem_u32(sW0);

    if (tid < 128) {
        sXi[tid] = xb[(size_t)I0 * NC + tid];
        srow[tid] = 0.f;
        // per-row source pointers for the (pipelined) prologue
        int r = tid;
        int J;
        if (isDiag) J = (r == 127) ? jbase : (jbase + 1 + r + ((r < rsplit) ? pp : 0));
        else        J = jbase + r;
        sRowJ[r]  = xb + (size_t)J * NC;
        sRowXi[r] = sXi + ((r < rsplit) ? 0 : 128);
    } else if (tid < 256) {
        sXi[tid] = xb[(size_t)I1 * NC + (tid - 128)];
    }
    if (tid < 192) { sBias[tid] = b1[tid]; sBias[192 + tid] = b2[tid]; }
    if (tid < 96)  { sBias[384 + tid] = b3[tid]; sBias[480 + tid] = b4[tid]; sW5[tid] = w5[tid]; }
    if (tid == 0)  sB5 = b5[0];

    // stage w1 chunks 0,1 immediately (slots 0,1; overlaps xi staging + prologue)
    stage_chunk32(w1,      192, 128, sw0_bytes,              tid);
    stage_chunk32(w1 + 32, 192, 128, sw0_bytes + WBUF_BYTES, tid);
    __syncthreads();   // sXi / sRowJ / sRowXi ready

    // pre-layer prologue: only A chunks 0,1 (chunks 2,3 pipelined inside layer 1)
    prologue_chunk(buf, 132, 0, sRowJ, sRowXi, tid);
    prologue_chunk(buf, 132, 1, sRowJ, sRowXi, tid);
    // layer entry performs CP_WAIT0 + __syncthreads (orders prologue writes too)

    // ring BASE per layer: 0, (0+4)&3=0, (0+6)&3=2, (2+6)&3=0
    layer<192, 128, 132, 196, 192, 192, 0, true,  false>(buf, w1, sBias + 0,   w2, sW0, sw0_bytes, sW5, srow, sRowJ, sRowXi, tid);
    layer<192, 192, 196, 196,  96, 192, 0, false, false>(buf, w2, sBias + 192, w3, sW0, sw0_bytes, sW5, srow, sRowJ, sRowXi, tid);
    layer< 96, 192, 196, 100,  96,  96, 2, false, false>(buf, w3, sBias + 384, w4, sW0, sw0_bytes, sW5, srow, sRowJ, sRowXi, tid);
    layer< 96,  96, 100, 100,   0,   0, 0, false, true >(buf, w4, sBias + 480, (const float*)0, sW0, sw0_bytes, sW5, srow, sRowJ, sRowXi, tid);
    __syncthreads();   // srow atomics visible

    // write logits (fused L5 already accumulated in srow)
    if (tid < 128 && !(isDiag && tid == 127)) {
        float lg = srow[tid] + sB5;
        int I = (tid < rsplit) ? I0 : I1;
        int J;
        if (isDiag) J = jbase + 1 + tid + ((tid < rsplit) ? pp : 0);
        else        J = jbase + tid;
        g_logits[((size_t)b * NN + I) * NN + J] = lg;   // direct
        g_logits[((size_t)b * NN + J) * NN + I] = lg;   // mirror (d symmetric)
    }
}

__global__ void __launch_bounds__(256)
softmax_kernel(float2* __restrict__ out)
{
    __shared__ float sred[8];
    __shared__ float sval;
    int row = blockIdx.x;
    int i   = row & (NN - 1);
    const float* L = g_logits + (size_t)row * NN;
    int tid  = threadIdx.x;
    int lane = tid & 31, warp = tid >> 5;

    // self-edge masked exactly (diagonal logits are never computed)
    float l0 = (tid == i)       ? -1e8f : L[tid];
    float l1 = (tid + 256 == i) ? -1e8f : L[tid + 256];

    float m = fmaxf(l0, l1);
#pragma unroll
    for (int o = 16; o > 0; o >>= 1) m = fmaxf(m, __shfl_xor_sync(0xffffffffu, m, o));
    if (lane == 0) sred[warp] = m;
    __syncthreads();
    if (tid == 0) {
        float v = sred[0];
        for (int w = 1; w < 8; ++w) v = fmaxf(v, sred[w]);
        sval = v;
    }
    __syncthreads();
    float M  = sval;
    float e0 = expf(l0 - M);
    float e1 = expf(l1 - M);
    float s  = e0 + e1;
#pragma unroll
    for (int o = 16; o > 0; o >>= 1) s += __shfl_xor_sync(0xffffffffu, s, o);
    __syncthreads();
    if (lane == 0) sred[warp] = s;
    __syncthreads();
    if (tid == 0) {
        float v = 0.f;
        for (int w = 0; w < 8; ++w) v += sred[w];
        sval = 1.0f / v;
    }
    __syncthreads();
    float inv = sval;

    float2* o2 = out + (size_t)row * NN;
    o2[tid]       = make_float2(tid == i ? 1.f : 0.f,       e0 * inv);
    o2[tid + 256] = make_float2(tid + 256 == i ? 1.f : 0.f, e1 * inv);
}

extern "C" void kernel_launch(void* const* d_in, const int* in_sizes, int n_in,
                              void* d_out, int out_size)
{
    const float* x  = (const float*)d_in[0];
    // d_in[1] = W_id (exact identity; regenerated analytically)
    const float* w1 = (const float*)d_in[2];
    const float* b1 = (const float*)d_in[3];
    const float* w2 = (const float*)d_in[4];
    const float* b2 = (const float*)d_in[5];
    const float* w3 = (const float*)d_in[6];
    const float* b3 = (const float*)d_in[7];
    const float* w4 = (const float*)d_in[8];
    const float* b4 = (const float*)d_in[9];
    const float* w5 = (const float*)d_in[10];
    const float* b5 = (const float*)d_in[11];
    float2* out = (float2*)d_out;

    // dyn smem: act buf 128x196 + 4-slot weight ring 4x6912 = 52736 words = 210,944 B
    size_t smem_bytes = (128 * 196 + 4 * WBUF_WORDS) * sizeof(uint32_t);
    cudaFuncSetAttribute(mlp_kernel, cudaFuncAttributeMaxDynamicSharedMemorySize,
                         (int)smem_bytes);

    // exact-dedup tile set: 4 batches x 1024 CTAs
    mlp_kernel<<<NB * 1024, 512, smem_bytes>>>(
        x, w1, b1, w2, b2, w3, b3, w4, b4, w5, b5);
    softmax_kernel<<<NB * NN, 256>>>(out);
}